// round 3
// baseline (speedup 1.0000x reference)
#include <cuda_runtime.h>
#include <math.h>
#include <stdint.h>

#define NUM_LEVEL 16
#define N_POINTS  262144

struct LevelMeta {
    float    scale;    // 2^(l*log2(1.38191288))*16 - 1
    uint32_t res;      // ceil(scale)+1
    uint32_t offset;   // table offset (in float2 entries)
    uint32_t mask;     // hsize-1 for hashed levels (hsize = 2^19)
    uint32_t hashed;   // 1 if hash path, 0 if dense path
    uint32_t pad;
};

struct Meta {
    LevelMeta lv[NUM_LEVEL];
};

__global__ void __launch_bounds__(256)
grid_encode_kernel(const float* __restrict__ pts,
                   const float2* __restrict__ emb,
                   float2* __restrict__ out,
                   Meta meta)
{
    const uint32_t tid = blockIdx.x * blockDim.x + threadIdx.x;
    if (tid >= (uint32_t)N_POINTS * NUM_LEVEL) return;

    const uint32_t n = tid >> 4;     // point index
    const uint32_t l = tid & 15;     // level index

    // 16 consecutive threads share one point: L1 broadcast
    const float inx = __ldg(pts + n * 3 + 0);
    const float iny = __ldg(pts + n * 3 + 1);
    const float inz = __ldg(pts + n * 3 + 2);

    const LevelMeta m = meta.lv[l];

    const float px = (inx + 1.0f) * 0.5f * m.scale;
    const float py = (iny + 1.0f) * 0.5f * m.scale;
    const float pz = (inz + 1.0f) * 0.5f * m.scale;

    const float gx = floorf(px), gy = floorf(py), gz = floorf(pz);
    const float fx = px - gx,   fy = py - gy,   fz = pz - gz;

    const uint32_t ix = (uint32_t)gx;
    const uint32_t iy = (uint32_t)gy;
    const uint32_t iz = (uint32_t)gz;

    const float wx[2] = {1.0f - fx, fx};
    const float wy[2] = {1.0f - fy, fy};
    const float wz[2] = {1.0f - fz, fz};

    const float2* __restrict__ table = emb + m.offset;
    const uint32_t r  = m.res;
    const uint32_t r2 = r * r;
    const uint32_t mask = m.mask;

    float accx = 0.0f, accy = 0.0f;

    if (m.hashed) {
        // Hashed levels: random gathers over 4MB tables -> zero L1 reuse.
        // Use L2-only loads (.cg) so they don't thrash the dense tables out of L1.
        uint32_t idx[8];
        #pragma unroll
        for (int c = 0; c < 8; ++c) {
            const uint32_t cx = ix + (uint32_t)(c & 1);
            const uint32_t cy = iy + (uint32_t)((c >> 1) & 1);
            const uint32_t cz = iz + (uint32_t)(c >> 2);
            idx[c] = (cx ^ (cy * 2654435761u) ^ (cz * 805459861u)) & mask;
        }
        #pragma unroll
        for (int c = 0; c < 8; ++c) {
            const float w = wx[c & 1] * wy[(c >> 1) & 1] * wz[c >> 2];
            const float2 f = __ldcg(table + idx[c]);
            accx = fmaf(w, f.x, accx);
            accy = fmaf(w, f.y, accy);
        }
    } else {
        // Dense levels: small tables (32KB..1.6MB) -> keep L1-allocating loads,
        // tables for levels 0-2 become effectively L1-resident per SM.
        uint32_t idx[8];
        #pragma unroll
        for (int c = 0; c < 8; ++c) {
            const uint32_t cx = ix + (uint32_t)(c & 1);
            const uint32_t cy = iy + (uint32_t)((c >> 1) & 1);
            const uint32_t cz = iz + (uint32_t)(c >> 2);
            idx[c] = cx + cy * r + cz * r2;   // provably < hsize, no mod
        }
        #pragma unroll
        for (int c = 0; c < 8; ++c) {
            const float w = wx[c & 1] * wy[(c >> 1) & 1] * wz[c >> 2];
            const float2 f = __ldg(table + idx[c]);
            accx = fmaf(w, f.x, accx);
            accy = fmaf(w, f.y, accy);
        }
    }

    // out[n, l] -> contiguous float2 per warp; evict-first (never re-read)
    __stcs(out + n * (uint32_t)NUM_LEVEL + l, make_float2(accx, accy));
}

// Host-side meta computation, bit-matching the reference's double-precision math.
static void compute_meta(Meta& M)
{
    const double ls = 1.38191288;
    const double lg = log2(ls);
    uint32_t off = 0;
    for (int i = 0; i < NUM_LEVEL; ++i) {
        double s   = exp2((double)i * lg) * 16.0 - 1.0;
        int    res = (int)ceil(s) + 1;

        double   res_meta = ceil(16.0 * pow(ls, (double)i));
        double   p3 = res_meta * res_meta * res_meta;
        uint32_t p  = (p3 > 524288.0) ? 524288u : (uint32_t)p3;
        p = ((p + 7u) / 8u) * 8u;

        unsigned long long res3 =
            (unsigned long long)res * (unsigned long long)res * (unsigned long long)res;
        bool hashed = res3 > (unsigned long long)p;

        M.lv[i].scale  = (float)s;
        M.lv[i].res    = (uint32_t)res;
        M.lv[i].offset = off;
        M.lv[i].mask   = p - 1u;   // valid for hashed levels (p = 2^19)
        M.lv[i].hashed = hashed ? 1u : 0u;
        M.lv[i].pad    = 0;

        off += p;
    }
}

extern "C" void kernel_launch(void* const* d_in, const int* in_sizes, int n_in,
                              void* d_out, int out_size)
{
    const float*  pts = (const float*)d_in[0];   // [N_POINTS, 3]
    const float2* emb = (const float2*)d_in[1];  // [offs[-1], 2]
    float2*       out = (float2*)d_out;          // [N_POINTS, 16] float2

    Meta M;
    compute_meta(M);

    const uint32_t total   = (uint32_t)N_POINTS * NUM_LEVEL;
    const uint32_t threads = 256;
    const uint32_t blocks  = (total + threads - 1) / threads;

    grid_encode_kernel<<<blocks, threads>>>(pts, emb, out, M);
}

// round 4
// speedup vs baseline: 1.1811x; 1.1811x over previous
#include <cuda_runtime.h>
#include <math.h>
#include <stdint.h>

#define NUM_LEVEL 16
#define N_POINTS  262144

struct LevelMeta {
    float    scale;
    uint32_t res;
    uint32_t offset;   // in float2 entries
    uint32_t mask;     // hsize-1 (hashed levels: hsize = 2^19)
    uint32_t hashed;
    uint32_t pad;
};

struct Meta {
    LevelMeta lv[NUM_LEVEL];
};

// One thread = one point x TWO consecutive levels -> 16 independent gathers
// in flight per thread, one float4 store.
__global__ void __launch_bounds__(256)
grid_encode_kernel(const float* __restrict__ pts,
                   const float2* __restrict__ emb,
                   float4* __restrict__ out,
                   Meta meta)
{
    const uint32_t tid = blockIdx.x * blockDim.x + threadIdx.x;
    if (tid >= (uint32_t)N_POINTS * (NUM_LEVEL / 2)) return;

    const uint32_t n  = tid >> 3;    // point index
    const uint32_t lp = tid & 7;     // level-pair index (levels 2*lp, 2*lp+1)

    // 8 consecutive threads share one point: L1 broadcast
    const float inx = __ldg(pts + n * 3 + 0);
    const float iny = __ldg(pts + n * 3 + 1);
    const float inz = __ldg(pts + n * 3 + 2);

    const float x01 = (inx + 1.0f) * 0.5f;
    const float y01 = (iny + 1.0f) * 0.5f;
    const float z01 = (inz + 1.0f) * 0.5f;

    uint32_t idx[2][8];
    float    wgt[2][8];
    const float2* __restrict__ tab[2];

    #pragma unroll
    for (int k = 0; k < 2; ++k) {
        const LevelMeta m = meta.lv[lp * 2 + k];

        const float px = x01 * m.scale;
        const float py = y01 * m.scale;
        const float pz = z01 * m.scale;

        const float gx = floorf(px), gy = floorf(py), gz = floorf(pz);
        const float fx = px - gx,   fy = py - gy,   fz = pz - gz;

        const uint32_t ix = (uint32_t)gx;
        const uint32_t iy = (uint32_t)gy;
        const uint32_t iz = (uint32_t)gz;

        const float wx[2] = {1.0f - fx, fx};
        const float wy[2] = {1.0f - fy, fy};
        const float wz[2] = {1.0f - fz, fz};

        const uint32_t r    = m.res;
        const uint32_t r2   = r * r;
        const uint32_t mask = m.mask;
        const uint32_t hashed = m.hashed;

        tab[k] = emb + m.offset;

        #pragma unroll
        for (int c = 0; c < 8; ++c) {
            const uint32_t bx = (uint32_t)(c & 1);
            const uint32_t by = (uint32_t)((c >> 1) & 1);
            const uint32_t bz = (uint32_t)(c >> 2);
            const uint32_t cx = ix + bx;
            const uint32_t cy = iy + by;
            const uint32_t cz = iz + bz;

            const uint32_t hidx = (cx ^ (cy * 2654435761u) ^ (cz * 805459861u)) & mask;
            const uint32_t didx = cx + cy * r + cz * r2;   // < hsize by construction
            idx[k][c] = hashed ? hidx : didx;
            wgt[k][c] = wx[bx] * wy[by] * wz[bz];
        }
    }

    // 16 independent gathers, front-batched for maximum MLP
    float2 f[2][8];
    #pragma unroll
    for (int k = 0; k < 2; ++k)
        #pragma unroll
        for (int c = 0; c < 8; ++c)
            f[k][c] = __ldg(tab[k] + idx[k][c]);

    float a0x = 0.0f, a0y = 0.0f, a1x = 0.0f, a1y = 0.0f;
    #pragma unroll
    for (int c = 0; c < 8; ++c) {
        a0x = fmaf(wgt[0][c], f[0][c].x, a0x);
        a0y = fmaf(wgt[0][c], f[0][c].y, a0y);
        a1x = fmaf(wgt[1][c], f[1][c].x, a1x);
        a1y = fmaf(wgt[1][c], f[1][c].y, a1y);
    }

    // out[n, lp] covers levels (2lp, 2lp+1) -> one coalesced 16B store
    out[n * (uint32_t)(NUM_LEVEL / 2) + lp] = make_float4(a0x, a0y, a1x, a1y);
}

// Host-side meta, bit-matching the reference's double-precision math.
static void compute_meta(Meta& M)
{
    const double ls = 1.38191288;
    const double lg = log2(ls);
    uint32_t off = 0;
    for (int i = 0; i < NUM_LEVEL; ++i) {
        double s   = exp2((double)i * lg) * 16.0 - 1.0;
        int    res = (int)ceil(s) + 1;

        double   res_meta = ceil(16.0 * pow(ls, (double)i));
        double   p3 = res_meta * res_meta * res_meta;
        uint32_t p  = (p3 > 524288.0) ? 524288u : (uint32_t)p3;
        p = ((p + 7u) / 8u) * 8u;

        unsigned long long res3 =
            (unsigned long long)res * (unsigned long long)res * (unsigned long long)res;
        bool hashed = res3 > (unsigned long long)p;

        M.lv[i].scale  = (float)s;
        M.lv[i].res    = (uint32_t)res;
        M.lv[i].offset = off;
        M.lv[i].mask   = p - 1u;
        M.lv[i].hashed = hashed ? 1u : 0u;
        M.lv[i].pad    = 0;

        off += p;
    }
}

extern "C" void kernel_launch(void* const* d_in, const int* in_sizes, int n_in,
                              void* d_out, int out_size)
{
    const float*  pts = (const float*)d_in[0];   // [N_POINTS, 3]
    const float2* emb = (const float2*)d_in[1];  // [offs[-1], 2]
    float4*       out = (float4*)d_out;          // [N_POINTS, 8] float4

    Meta M;
    compute_meta(M);

    const uint32_t total   = (uint32_t)N_POINTS * (NUM_LEVEL / 2);
    const uint32_t threads = 256;
    const uint32_t blocks  = (total + threads - 1) / threads;

    grid_encode_kernel<<<blocks, threads>>>(pts, emb, out, M);
}